// round 11
// baseline (speedup 1.0000x reference)
#include <cuda_runtime.h>
#include <mma.h>

using namespace nvcuda;

#define N_NODES 100000
#define N_EDGES 1600000
#define D_F     128
#define D_CAT   256
#define D_U1    214
#define D_U2    172
#define D_OUT   128

#define NWARP    9
#define ETHREADS (NWARP * 32)
#define N_TILES  (N_EDGES / 16)      // 100000 16-edge tiles
#define EGRID    148
#define WSTRIDE  (EGRID * NWARP)     // 1332

// ---- k_edge smem byte offsets ----
#define SB_W2   0                    // [128 f][132] tf32 : 67584 B
#define SB_W3   67584                // 67584 B
#define SB_B2M  135168               // bias2 matrix [128][16] : 8192 B
#define SB_W1P  143360               // w1 padded [128][8] : 4096 B
#define SB_B1   147456               // 512 B
#define SB_HB   147968               // per-warp 2176 floats (8704 B) x 9 = 78336
#define EDGE_SMEM_BYTES 226304

// ---------------- scratch ----------------
__device__ float g_aggr[N_NODES * D_F];
__device__ float g_nrm [N_NODES * D_CAT];
__device__ float g_u1  [N_NODES * D_U1];
__device__ float g_u2  [N_NODES * D_U2];

// ---------------- helpers ----------------
__device__ __forceinline__ float leaky(float v) { return v > 0.f ? v : 0.01f * v; }

__device__ __forceinline__ float tf32f(float x) {
    unsigned r; asm("cvt.rna.tf32.f32 %0, %1;" : "=r"(r) : "f"(x));
    return __uint_as_float(r);
}
__device__ __forceinline__ void red_v4(float* p, float a, float b, float c, float d) {
    asm volatile("red.global.add.v4.f32 [%0], {%1, %2, %3, %4};"
                 :: "l"(p), "f"(a), "f"(b), "f"(c), "f"(d) : "memory");
}
__device__ __forceinline__ unsigned long long pk(float x, float y) {
    unsigned long long r;
    asm("mov.b64 %0, {%1, %2};" : "=l"(r) : "f"(x), "f"(y));
    return r;
}
__device__ __forceinline__ float2 upk(unsigned long long v) {
    float2 f;
    asm("mov.b64 {%0, %1}, %2;" : "=f"(f.x), "=f"(f.y) : "l"(v));
    return f;
}
__device__ __forceinline__ unsigned long long fma2(unsigned long long a,
                                                   unsigned long long b,
                                                   unsigned long long c) {
    unsigned long long d;
    asm("fma.rn.f32x2 %0, %1, %2, %3;" : "=l"(d) : "l"(a), "l"(b), "l"(c));
    return d;
}

// ---------------- kernel: nop (ncu capture alignment) ----------------
__global__ void k_nop() {}

// ---------------- kernel: zero aggr scratch ----------------
__global__ void k_zero() {
    const int n4 = (N_NODES * D_F) / 4;
    float4* p = reinterpret_cast<float4*>(g_aggr);
    for (int i = blockIdx.x * blockDim.x + threadIdx.x; i < n4; i += gridDim.x * blockDim.x)
        p[i] = make_float4(0.f, 0.f, 0.f, 0.f);
}

// ---------------- kernel: edge MLP — warp-autonomous wmma tf32 ----------------
// Each warp owns 16 edges/tile through all 3 layers. No __syncthreads in loop.
__global__ void __launch_bounds__(ETHREADS, 1)
k_edge(const float* __restrict__ edge_attr,
       const int* __restrict__ edge_index,
       const float* __restrict__ Wm1, const float* __restrict__ bm1,
       const float* __restrict__ Wm2, const float* __restrict__ bm2,
       const float* __restrict__ Wm3, const float* __restrict__ bm3)
{
    extern __shared__ char smem[];
    float* w2s = reinterpret_cast<float*>(smem + SB_W2);
    float* w3s = reinterpret_cast<float*>(smem + SB_W3);
    float* b2m = reinterpret_cast<float*>(smem + SB_B2M);
    float* w1p = reinterpret_cast<float*>(smem + SB_W1P);
    float* b1s = reinterpret_cast<float*>(smem + SB_B1);

    const int tid = threadIdx.x;
    const int wid = tid >> 5;
    const int l   = tid & 31;
    float* hb = reinterpret_cast<float*>(smem + SB_HB) + wid * 2176;

    // ---- stage shared weights (block-wide, once) ----
    for (int i = tid; i < 128 * 128; i += ETHREADS) {
        const int f = i >> 7, k = i & 127;
        w2s[f * 132 + k] = tf32f(Wm2[i]);
        w3s[f * 132 + k] = tf32f(Wm3[i]);
    }
    for (int i = tid; i < 128 * 16; i += ETHREADS) b2m[i] = bm2[i >> 4];
    for (int i = tid; i < 128 * 8; i += ETHREADS) {
        const int f = i >> 3, j = i & 7;
        w1p[i] = (j < 5) ? Wm1[f * 5 + j] : 0.f;
    }
    if (tid < 128) b1s[tid] = bm1[tid];
    __syncthreads();

    const float4 bb3 = *reinterpret_cast<const float4*>(bm3 + 4 * l);
    const int e_ = l & 15;
    const int fh = l >> 4;

    const int gw = blockIdx.x * NWARP + wid;

    // per-warp prefetch
    float4 pf_attr = make_float4(0.f, 0.f, 0.f, 0.f);
    int    pf_dst = 0;
    if (gw < N_TILES) {
        if (l < 20) pf_attr = *reinterpret_cast<const float4*>(edge_attr + (long long)gw * 80 + 4 * l);
        if (l < 16) pf_dst = edge_index[N_EDGES + gw * 16 + l];
    }

    for (int tile = gw; tile < N_TILES; tile += WSTRIDE) {
        // stage attrs to warp buffer, keep dst in reg
        if (l < 20) *reinterpret_cast<float4*>(hb + 4 * l) = pf_attr;
        const int dreg = pf_dst;
        __syncwarp();
        float a0 = hb[e_ * 5 + 0], a1 = hb[e_ * 5 + 1], a2 = hb[e_ * 5 + 2],
              a3 = hb[e_ * 5 + 3], a4 = hb[e_ * 5 + 4];
        __syncwarp();

        // issue next prefetch
        {
            const int tn = tile + WSTRIDE;
            if (tn < N_TILES) {
                if (l < 20) pf_attr = *reinterpret_cast<const float4*>(edge_attr + (long long)tn * 80 + 4 * l);
                if (l < 16) pf_dst = edge_index[N_EDGES + tn * 16 + l];
            }
        }

        // ---- layer 1: 5 -> 128, write hb[k=f][e] pitch 16 ----
#pragma unroll 8
        for (int i = 0; i < 64; i++) {
            const int f = fh * 64 + i;
            const float4 wv = *reinterpret_cast<const float4*>(w1p + f * 8);
            const float w4 = w1p[f * 8 + 4];
            float v = b1s[f];
            v = fmaf(wv.x, a0, v); v = fmaf(wv.y, a1, v);
            v = fmaf(wv.z, a2, v); v = fmaf(wv.w, a3, v);
            v = fmaf(w4, a4, v);
            hb[f * 16 + e_] = tf32f(leaky(v));
        }
        __syncwarp();

        // ---- load B fragments (warp-private activations -> regs) ----
        wmma::fragment<wmma::matrix_b, 16, 16, 8, wmma::precision::tf32, wmma::row_major> b[16];
#pragma unroll
        for (int kt = 0; kt < 16; kt++)
            wmma::load_matrix_sync(b[kt], hb + kt * 128, 16);
        __syncwarp();

        // ---- layer 2: for each f-tile pair: acc = bias; 16 mma; leaky; store [k][e] ----
#pragma unroll
        for (int ftp = 0; ftp < 4; ftp++) {
            const int ft0 = 2 * ftp, ft1 = ft0 + 1;
            wmma::fragment<wmma::accumulator, 16, 16, 8, float> ac0, ac1;
            wmma::load_matrix_sync(ac0, b2m + ft0 * 256, 16, wmma::mem_row_major);
            wmma::load_matrix_sync(ac1, b2m + ft1 * 256, 16, wmma::mem_row_major);
#pragma unroll
            for (int kt = 0; kt < 16; kt++) {
                wmma::fragment<wmma::matrix_a, 16, 16, 8, wmma::precision::tf32, wmma::row_major> af0, af1;
                wmma::load_matrix_sync(af0, w2s + ft0 * 16 * 132 + kt * 8, 132);
                wmma::load_matrix_sync(af1, w2s + ft1 * 16 * 132 + kt * 8, 132);
                wmma::mma_sync(ac0, af0, b[kt], ac0);
                wmma::mma_sync(ac1, af1, b[kt], ac1);
            }
#pragma unroll
            for (int i = 0; i < ac0.num_elements; i++) {
                ac0.x[i] = tf32f(leaky(ac0.x[i]));
                ac1.x[i] = tf32f(leaky(ac1.x[i]));
            }
            wmma::store_matrix_sync(hb + ft0 * 256, ac0, 16, wmma::mem_row_major);
            wmma::store_matrix_sync(hb + ft1 * 256, ac1, 16, wmma::mem_row_major);
        }
        __syncwarp();

        // ---- reload B fragments from layer-2 output ----
#pragma unroll
        for (int kt = 0; kt < 16; kt++)
            wmma::load_matrix_sync(b[kt], hb + kt * 128, 16);
        __syncwarp();

        // ---- layer 3: acc = 0; 16 mma; store TRANSPOSED msg_t[e][132] ----
#pragma unroll
        for (int ftp = 0; ftp < 4; ftp++) {
            const int ft0 = 2 * ftp, ft1 = ft0 + 1;
            wmma::fragment<wmma::accumulator, 16, 16, 8, float> ac0, ac1;
            wmma::fill_fragment(ac0, 0.f);
            wmma::fill_fragment(ac1, 0.f);
#pragma unroll
            for (int kt = 0; kt < 16; kt++) {
                wmma::fragment<wmma::matrix_a, 16, 16, 8, wmma::precision::tf32, wmma::row_major> af0, af1;
                wmma::load_matrix_sync(af0, w3s + ft0 * 16 * 132 + kt * 8, 132);
                wmma::load_matrix_sync(af1, w3s + ft1 * 16 * 132 + kt * 8, 132);
                wmma::mma_sync(ac0, af0, b[kt], ac0);
                wmma::mma_sync(ac1, af1, b[kt], ac1);
            }
            wmma::store_matrix_sync(hb + ft0 * 16, ac0, 132, wmma::mem_col_major);
            wmma::store_matrix_sync(hb + ft1 * 16, ac1, 132, wmma::mem_col_major);
        }
        __syncwarp();

        // ---- scatter: per edge, coalesced 512B red.v4 (bias3 folded here) ----
#pragma unroll 4
        for (int e = 0; e < 16; e++) {
            const int d = __shfl_sync(0xffffffffu, dreg, e);
            const float4 v = *reinterpret_cast<const float4*>(hb + e * 132 + 4 * l);
            red_v4(g_aggr + (long long)d * D_F + 4 * l,
                   v.x + bb3.x, v.y + bb3.y, v.z + bb3.z, v.w + bb3.w);
        }
        __syncwarp();
    }
}

// ---------------- kernel: LayerNorm over concat(x, aggr) ----------------
__global__ void k_ln(const float* __restrict__ x,
                     const float* __restrict__ ln_g,
                     const float* __restrict__ ln_b)
{
    const int node = (blockIdx.x * blockDim.x + threadIdx.x) >> 5;
    const int lane = threadIdx.x & 31;
    if (node >= N_NODES) return;

    const float* xr = x      + (long long)node * D_F;
    const float* ar = g_aggr + (long long)node * D_F;
    float v[8];
#pragma unroll
    for (int i = 0; i < 4; i++) v[i]     = xr[lane + 32 * i];
#pragma unroll
    for (int i = 0; i < 4; i++) v[4 + i] = ar[lane + 32 * i];

    float s = 0.f;
#pragma unroll
    for (int i = 0; i < 8; i++) s += v[i];
#pragma unroll
    for (int o = 16; o > 0; o >>= 1) s += __shfl_xor_sync(0xffffffffu, s, o);
    const float mu = s * (1.0f / 256.0f);

    float q = 0.f;
#pragma unroll
    for (int i = 0; i < 8; i++) { const float d = v[i] - mu; q += d * d; }
#pragma unroll
    for (int o = 16; o > 0; o >>= 1) q += __shfl_xor_sync(0xffffffffu, q, o);
    const float rstd = rsqrtf(q * (1.0f / 256.0f) + 1e-5f);

    float* out = g_nrm + (long long)node * D_CAT;
#pragma unroll
    for (int i = 0; i < 8; i++) {
        const int c = (i < 4) ? (lane + 32 * i) : (128 + lane + 32 * (i - 4));
        out[c] = (v[i] - mu) * rstd * ln_g[c] + ln_b[c];
    }
}

// ---------------- kernel: wmma tf32 GEMM (R8-measured version) ----------------
// 64x64 tile, 8 warps (2m x 4n), each warp 32m x 16n.
__global__ void __launch_bounds__(256)
k_wgemm(const float* __restrict__ A, const float* __restrict__ B,
        const float* __restrict__ bias, float* __restrict__ C,
        int M, int N, int K, int doLeaky)
{
    __shared__ float As[64 * 36];
    __shared__ float Bs[64 * 36];
    __shared__ float bmat[16 * 68];

    const int tid = threadIdx.x;
    const int w  = tid >> 5;
    const int wm = w >> 2;    // 0..1
    const int wn = w & 3;     // 0..3
    int m0 = blockIdx.x * 64; if (m0 > M - 64) m0 = M - 64;
    int n0 = blockIdx.y * 64; if (n0 > N - 64) n0 = N - 64;

    for (int i = tid; i < 16 * 64; i += 256) {
        const int r = i >> 6, c = i & 63;
        bmat[r * 68 + c] = bias[n0 + c];
    }
    __syncthreads();

    wmma::fragment<wmma::accumulator, 16, 16, 8, float> acc0, acc1;
    wmma::load_matrix_sync(acc0, bmat + wn * 16, 68, wmma::mem_row_major);
    acc1 = acc0;
    __syncthreads();

    for (int k0 = 0; k0 < K; k0 += 32) {
#pragma unroll
        for (int r = 0; r < 8; r++) {
            const int i = tid + r * 256;
            const int mm = i >> 5, kk = i & 31;
            const int ka = k0 + kk;
            As[mm * 36 + kk] = (ka < K) ? tf32f(A[(long long)(m0 + mm) * K + ka]) : 0.f;
            Bs[mm * 36 + kk] = (ka < K) ? tf32f(B[(long long)(n0 + mm) * K + ka]) : 0.f;
        }
        __syncthreads();
#pragma unroll
        for (int kt = 0; kt < 4; kt++) {
            wmma::fragment<wmma::matrix_a, 16, 16, 8, wmma::precision::tf32, wmma::row_major> af0, af1;
            wmma::fragment<wmma::matrix_b, 16, 16, 8, wmma::precision::tf32, wmma::col_major> bf;
            wmma::load_matrix_sync(af0, As + (wm * 32) * 36 + kt * 8, 36);
            wmma::load_matrix_sync(af1, As + (wm * 32 + 16) * 36 + kt * 8, 36);
            wmma::load_matrix_sync(bf, Bs + (wn * 16) * 36 + kt * 8, 36);
            wmma::mma_sync(acc0, af0, bf, acc0);
            wmma::mma_sync(acc1, af1, bf, acc1);
        }
        __syncthreads();
    }

    if (doLeaky) {
#pragma unroll
        for (int i = 0; i < acc0.num_elements; i++) {
            acc0.x[i] = leaky(acc0.x[i]);
            acc1.x[i] = leaky(acc1.x[i]);
        }
    }
    wmma::store_matrix_sync(C + (long long)(m0 + wm * 32) * N + n0 + wn * 16,
                            acc0, N, wmma::mem_row_major);
    wmma::store_matrix_sync(C + (long long)(m0 + wm * 32 + 16) * N + n0 + wn * 16,
                            acc1, N, wmma::mem_row_major);
}

// ---------------- launch ----------------
extern "C" void kernel_launch(void* const* d_in, const int* in_sizes, int n_in,
                              void* d_out, int out_size)
{
    const float* x          = (const float*)d_in[0];
    const int*   edge_index = (const int*)d_in[1];
    const float* edge_attr  = (const float*)d_in[2];
    const float* Wm1 = (const float*)d_in[3];
    const float* bm1 = (const float*)d_in[4];
    const float* Wm2 = (const float*)d_in[5];
    const float* bm2 = (const float*)d_in[6];
    const float* Wm3 = (const float*)d_in[7];
    const float* bm3 = (const float*)d_in[8];
    const float* ln_g = (const float*)d_in[9];
    const float* ln_b = (const float*)d_in[10];
    const float* Wu1 = (const float*)d_in[11];
    const float* bu1 = (const float*)d_in[12];
    const float* Wu2 = (const float*)d_in[13];
    const float* bu2 = (const float*)d_in[14];
    const float* Wu3 = (const float*)d_in[15];
    const float* bu3 = (const float*)d_in[16];
    float* out = (float*)d_out;

    void *p_nrm = nullptr, *p_u1 = nullptr, *p_u2 = nullptr;
    cudaGetSymbolAddress(&p_nrm, g_nrm);
    cudaGetSymbolAddress(&p_u1,  g_u1);
    cudaGetSymbolAddress(&p_u2,  g_u2);

    cudaFuncSetAttribute(k_edge, cudaFuncAttributeMaxDynamicSharedMemorySize, EDGE_SMEM_BYTES);

    k_zero<<<2048, 256>>>();
    k_nop<<<1, 32>>>();
    k_nop<<<1, 32>>>();

    k_edge<<<EGRID, ETHREADS, EDGE_SMEM_BYTES>>>(edge_attr, edge_index,
                                                 Wm1, bm1, Wm2, bm2, Wm3, bm3);

    k_ln<<<(N_NODES * 32 + 255) / 256, 256>>>(x, ln_g, ln_b);

    dim3 g1((N_NODES + 63) / 64, (D_U1 + 63) / 64);
    k_wgemm<<<g1, 256>>>((const float*)p_nrm, Wu1, bu1, (float*)p_u1,
                         N_NODES, D_U1, D_CAT, 1);

    dim3 g2((N_NODES + 63) / 64, (D_U2 + 63) / 64);
    k_wgemm<<<g2, 256>>>((const float*)p_u1, Wu2, bu2, (float*)p_u2,
                         N_NODES, D_U2, D_U1, 1);

    dim3 g3((N_NODES + 63) / 64, (D_OUT + 63) / 64);
    k_wgemm<<<g3, 256>>>((const float*)p_u2, Wu3, bu3, out,
                         N_NODES, D_OUT, D_U2, 0);
}

// round 12
// speedup vs baseline: 1.2721x; 1.2721x over previous
#include <cuda_runtime.h>
#include <mma.h>

using namespace nvcuda;

#define N_NODES 100000
#define N_EDGES 1600000
#define D_F     128
#define D_CAT   256
#define D_U1    214
#define D_U2    172
#define D_OUT   128

#define E_TILE   128
#define N_TILES  (N_EDGES / E_TILE)   // 12500
#define EGRID    148
#define HP 136                        // h pitch (floats)

// ---- k_edge dynamic smem byte offsets (R8-measured layout) ----
#define SB_H1   0                     // h1 [128][HP] : 69632 B
#define SB_H2   69632                 // h2 [128][HP] : 69632 B
#define SB_WST  139264                // weight staging / bias mats : 65536 B
#define SB_W1   204800                // 640 floats
#define SB_B1   207360
#define SB_B2   207872
#define SB_B3   208384
#define SB_EA   208896                // 2 x 640 floats
#define SB_DST  214016                // 2 x 128 ints
#define EDGE_SMEM_BYTES 215040

// ---------------- scratch ----------------
__device__ float g_aggr[N_NODES * D_F];
__device__ float g_nrm [N_NODES * D_CAT];
__device__ float g_u1  [N_NODES * D_U1];
__device__ float g_u2  [N_NODES * D_U2];
__device__ float g_w1t [D_U1 * D_CAT];
__device__ float g_w2t [D_U2 * D_U1];
__device__ float g_w3t [D_OUT * D_U2];

// ---------------- helpers ----------------
__device__ __forceinline__ float leaky(float v) { return v > 0.f ? v : 0.01f * v; }

__device__ __forceinline__ float tf32f(float x) {
    unsigned r; asm("cvt.rna.tf32.f32 %0, %1;" : "=r"(r) : "f"(x));
    return __uint_as_float(r);
}
__device__ __forceinline__ void red_f32(float* p, float v) {
    asm volatile("red.global.add.f32 [%0], %1;" :: "l"(p), "f"(v) : "memory");
}
__device__ __forceinline__ void cp_async4(unsigned saddr, const void* g) {
    asm volatile("cp.async.ca.shared.global [%0], [%1], 4;" :: "r"(saddr), "l"(g));
}
#define CP_COMMIT() asm volatile("cp.async.commit_group;" ::: "memory")
#define CP_WAIT(n)  asm volatile("cp.async.wait_group %0;" :: "n"(n) : "memory")

// ---------------- kernel: nop (ncu capture alignment) ----------------
__global__ void k_nop() {}

// ---------------- kernel: zero aggr scratch ----------------
__global__ void k_zero() {
    const int n4 = (N_NODES * D_F) / 4;
    float4* p = reinterpret_cast<float4*>(g_aggr);
    for (int i = blockIdx.x * blockDim.x + threadIdx.x; i < n4; i += gridDim.x * blockDim.x)
        p[i] = make_float4(0.f, 0.f, 0.f, 0.f);
}

// ---------------- kernel: pre-convert node-MLP weights to tf32 ----------------
__global__ void k_prep(const float* __restrict__ Wu1,
                       const float* __restrict__ Wu2,
                       const float* __restrict__ Wu3) {
    const int stride = gridDim.x * blockDim.x;
    const int t = blockIdx.x * blockDim.x + threadIdx.x;
    for (int i = t; i < D_U1 * D_CAT; i += stride) g_w1t[i] = tf32f(Wu1[i]);
    for (int i = t; i < D_U2 * D_U1; i += stride)  g_w2t[i] = tf32f(Wu2[i]);
    for (int i = t; i < D_OUT * D_U2; i += stride) g_w3t[i] = tf32f(Wu3[i]);
}

// ---------------- kernel: edge MLP (wmma tf32) — R8-measured best, verbatim ----------------
__global__ void __launch_bounds__(256, 1)
k_edge(const float* __restrict__ edge_attr,
       const int* __restrict__ edge_index,
       const float* __restrict__ Wm1, const float* __restrict__ bm1,
       const float* __restrict__ Wm2, const float* __restrict__ bm2,
       const float* __restrict__ Wm3, const float* __restrict__ bm3)
{
    extern __shared__ char smem[];
    float* h1  = reinterpret_cast<float*>(smem + SB_H1);
    float* h2  = reinterpret_cast<float*>(smem + SB_H2);
    float* wst = reinterpret_cast<float*>(smem + SB_WST);
    float* w1s = reinterpret_cast<float*>(smem + SB_W1);
    float* b1s = reinterpret_cast<float*>(smem + SB_B1);
    float* b2s = reinterpret_cast<float*>(smem + SB_B2);
    float* b3s = reinterpret_cast<float*>(smem + SB_B3);
    float* eab = reinterpret_cast<float*>(smem + SB_EA);
    int*   dsb = reinterpret_cast<int*>(smem + SB_DST);

    const int tid = threadIdx.x;
    const int w   = tid >> 5;
    const int l   = tid & 31;
    const int f0  = w * 16;

    for (int i = tid; i < 640; i += 256) w1s[i] = Wm1[i];
    if (tid < 128) { b1s[tid] = bm1[tid]; b2s[tid] = bm2[tid]; b3s[tid] = bm3[tid]; }

    wmma::fragment<wmma::matrix_a, 16, 16, 8, wmma::precision::tf32, wmma::row_major> a2[16], a3[16];
    for (int i = tid; i < 128 * 128; i += 256) wst[i] = tf32f(Wm2[i]);
    __syncthreads();
#pragma unroll
    for (int kt = 0; kt < 16; kt++)
        wmma::load_matrix_sync(a2[kt], wst + f0 * 128 + kt * 8, 128);
    __syncthreads();
    for (int i = tid; i < 128 * 128; i += 256) wst[i] = tf32f(Wm3[i]);
    __syncthreads();
#pragma unroll
    for (int kt = 0; kt < 16; kt++)
        wmma::load_matrix_sync(a3[kt], wst + f0 * 128 + kt * 8, 128);
    __syncthreads();

    float* bm2m = wst;          // [128][16]
    float* bm3m = wst + 2048;   // [128][16]
    for (int i = tid; i < 128 * 16; i += 256) {
        const int f = i >> 4;
        bm2m[i] = b2s[f];
        bm3m[i] = b3s[f];
    }
    __syncthreads();
    wmma::fragment<wmma::accumulator, 16, 16, 8, float> ab2, ab3;
    wmma::load_matrix_sync(ab2, bm2m + f0 * 16, 16, wmma::mem_row_major);
    wmma::load_matrix_sync(ab3, bm3m + f0 * 16, 16, wmma::mem_row_major);

    const int t0 = blockIdx.x;
    float4 ear = make_float4(0.f, 0.f, 0.f, 0.f);
    int    dsr = 0;
    if (tid < 160)
        reinterpret_cast<float4*>(eab)[tid] =
            reinterpret_cast<const float4*>(edge_attr + (long long)t0 * E_TILE * 5)[tid];
    if (tid < 128)
        dsb[tid] = edge_index[N_EDGES + t0 * E_TILE + tid];
    {
        const int t1 = (t0 + EGRID < N_TILES) ? t0 + EGRID : t0;
        if (tid < 160)
            ear = reinterpret_cast<const float4*>(edge_attr + (long long)t1 * E_TILE * 5)[tid];
        if (tid < 128)
            dsr = edge_index[N_EDGES + t1 * E_TILE + tid];
    }
    __syncthreads();

    const int fRow = (w & 3) * 32 + l;
    const int es0  = (w >> 2) * 64;

    int cur = 0;
    for (int tile = t0; tile < N_TILES; tile += EGRID) {
        const float* eas  = eab + cur * 640;
        const int*   dsti = dsb + cur * 128;

        // ---- layer 1: 5 -> 128, write h1[k=f][e] (tf32) ----
        {
            float a[20];
            const float4* ap = reinterpret_cast<const float4*>(&eas[(4 * l) * 5]);
#pragma unroll
            for (int q = 0; q < 5; q++) {
                const float4 v = ap[q];
                a[4*q] = v.x; a[4*q+1] = v.y; a[4*q+2] = v.z; a[4*q+3] = v.w;
            }
#pragma unroll
            for (int fi = 0; fi < 16; fi++) {
                const int f = f0 + fi;
                const float bb = b1s[f];
                float v[4];
#pragma unroll
                for (int ei = 0; ei < 4; ei++) {
                    float t = bb;
#pragma unroll
                    for (int j = 0; j < 5; j++)
                        t = fmaf(w1s[f * 5 + j], a[ei * 5 + j], t);
                    v[ei] = tf32f(leaky(t));
                }
                *reinterpret_cast<float4*>(&h1[f * HP + 4 * l]) =
                    make_float4(v[0], v[1], v[2], v[3]);
            }
        }
        __syncthreads();

        // ---- layer 2: h2 = tf32(leaky(W2 @ h1 + b2)), 2-wide n interleave ----
#pragma unroll 1
        for (int n = 0; n < 8; n += 2) {
            wmma::fragment<wmma::accumulator, 16, 16, 8, float> ac0 = ab2, ac1 = ab2;
#pragma unroll
            for (int kt = 0; kt < 16; kt++) {
                wmma::fragment<wmma::matrix_b, 16, 16, 8, wmma::precision::tf32, wmma::row_major> bf0, bf1;
                wmma::load_matrix_sync(bf0, h1 + kt * 8 * HP + n * 16, HP);
                wmma::load_matrix_sync(bf1, h1 + kt * 8 * HP + n * 16 + 16, HP);
                wmma::mma_sync(ac0, a2[kt], bf0, ac0);
                wmma::mma_sync(ac1, a2[kt], bf1, ac1);
            }
#pragma unroll
            for (int i = 0; i < ac0.num_elements; i++) {
                ac0.x[i] = tf32f(leaky(ac0.x[i]));
                ac1.x[i] = tf32f(leaky(ac1.x[i]));
            }
            wmma::store_matrix_sync(h2 + f0 * HP + n * 16, ac0, HP, wmma::mem_row_major);
            wmma::store_matrix_sync(h2 + f0 * HP + n * 16 + 16, ac1, HP, wmma::mem_row_major);
        }
        __syncthreads();

        // prefetch shuffle: regs -> other buffer, issue next LDG
        {
            const int nb = cur ^ 1;
            if (tid < 160) reinterpret_cast<float4*>(eab + nb * 640)[tid] = ear;
            if (tid < 128) dsb[nb * 128 + tid] = dsr;
            const int tn = tile + 2 * EGRID;
            const int tc = (tn < N_TILES) ? tn : t0;
            if (tid < 160)
                ear = reinterpret_cast<const float4*>(edge_attr + (long long)tc * E_TILE * 5)[tid];
            if (tid < 128)
                dsr = edge_index[N_EDGES + tc * E_TILE + tid];
        }

        // ---- layer 3: msg = W3 @ h2 + b3, store into h1 ----
#pragma unroll 1
        for (int n = 0; n < 8; n += 2) {
            wmma::fragment<wmma::accumulator, 16, 16, 8, float> ac0 = ab3, ac1 = ab3;
#pragma unroll
            for (int kt = 0; kt < 16; kt++) {
                wmma::fragment<wmma::matrix_b, 16, 16, 8, wmma::precision::tf32, wmma::row_major> bf0, bf1;
                wmma::load_matrix_sync(bf0, h2 + kt * 8 * HP + n * 16, HP);
                wmma::load_matrix_sync(bf1, h2 + kt * 8 * HP + n * 16 + 16, HP);
                wmma::mma_sync(ac0, a3[kt], bf0, ac0);
                wmma::mma_sync(ac1, a3[kt], bf1, ac1);
            }
            wmma::store_matrix_sync(h1 + f0 * HP + n * 16, ac0, HP, wmma::mem_row_major);
            wmma::store_matrix_sync(h1 + f0 * HP + n * 16 + 16, ac1, HP, wmma::mem_row_major);
        }
        __syncthreads();

        // ---- scatter: coalesced red.global.add per edge ----
        {
            const float* mrow = h1 + fRow * HP;
#pragma unroll 4
            for (int j = 0; j < 64; j++) {
                const int e = es0 + j;
                const int d = dsti[e];
                red_f32(&g_aggr[(long long)d * D_F + fRow], mrow[e]);
            }
        }
        __syncthreads();
        cur ^= 1;
    }
}

// ---------------- kernel: LayerNorm over concat(x, aggr), tf32 output ----------------
__global__ void k_ln(const float* __restrict__ x,
                     const float* __restrict__ ln_g,
                     const float* __restrict__ ln_b)
{
    const int node = (blockIdx.x * blockDim.x + threadIdx.x) >> 5;
    const int lane = threadIdx.x & 31;
    if (node >= N_NODES) return;

    const float* xr = x      + (long long)node * D_F;
    const float* ar = g_aggr + (long long)node * D_F;
    float v[8];
#pragma unroll
    for (int i = 0; i < 4; i++) v[i]     = xr[lane + 32 * i];
#pragma unroll
    for (int i = 0; i < 4; i++) v[4 + i] = ar[lane + 32 * i];

    float s = 0.f;
#pragma unroll
    for (int i = 0; i < 8; i++) s += v[i];
#pragma unroll
    for (int o = 16; o > 0; o >>= 1) s += __shfl_xor_sync(0xffffffffu, s, o);
    const float mu = s * (1.0f / 256.0f);

    float q = 0.f;
#pragma unroll
    for (int i = 0; i < 8; i++) { const float d = v[i] - mu; q += d * d; }
#pragma unroll
    for (int o = 16; o > 0; o >>= 1) q += __shfl_xor_sync(0xffffffffu, q, o);
    const float rstd = rsqrtf(q * (1.0f / 256.0f) + 1e-5f);

    float* out = g_nrm + (long long)node * D_CAT;
#pragma unroll
    for (int i = 0; i < 8; i++) {
        const int c = (i < 4) ? (lane + 32 * i) : (128 + lane + 32 * (i - 4));
        out[c] = tf32f((v[i] - mu) * rstd * ln_g[c] + ln_b[c]);
    }
}

// ---------------- kernel: wmma tf32 GEMM, cp.async double-buffered ----------------
// C = post(A[M,K] @ B[N,K]^T + bias). A and B hold tf32-valued floats already.
// 64x64 tile, 8 warps (2m x 4n), warp 32m x 16n. Block origin clamped.
__global__ void __launch_bounds__(256)
k_wgemm(const float* __restrict__ A, const float* __restrict__ B,
        const float* __restrict__ bias, float* __restrict__ C,
        int M, int N, int K, int doLeaky, int outCvt)
{
    __shared__ float As[2][64 * 36];
    __shared__ float Bs[2][64 * 36];
    __shared__ float bmat[16 * 68];

    const int tid = threadIdx.x;
    const int w  = tid >> 5;
    const int wm = w >> 2;    // 0..1
    const int wn = w & 3;     // 0..3
    int m0 = blockIdx.x * 64; if (m0 > M - 64) m0 = M - 64;
    int n0 = blockIdx.y * 64; if (n0 > N - 64) n0 = N - 64;

    for (int i = tid; i < 16 * 64; i += 256) {
        const int r = i >> 6, c = i & 63;
        bmat[r * 68 + c] = bias[n0 + c];
    }
    __syncthreads();

    wmma::fragment<wmma::accumulator, 16, 16, 8, float> acc0, acc1;
    wmma::load_matrix_sync(acc0, bmat + wn * 16, 68, wmma::mem_row_major);
    acc1 = acc0;

    const int mm = tid >> 5;            // staging row base: 8 rows per pass
    const int kk = tid & 31;
    const int nChunks = (K + 31) / 32;

    // stage chunk c into buffer b
    auto stage = [&](int c, int b) {
#pragma unroll
        for (int r = 0; r < 8; r++) {
            const int row = mm + r * 8;
            const int ka = c * 32 + kk;
            float* dA = &As[b][row * 36 + kk];
            float* dB = &Bs[b][row * 36 + kk];
            if (ka < K) {
                cp_async4((unsigned)__cvta_generic_to_shared(dA),
                          A + (long long)(m0 + row) * K + ka);
                cp_async4((unsigned)__cvta_generic_to_shared(dB),
                          B + (long long)(n0 + row) * K + ka);
            } else {
                *dA = 0.f;
                *dB = 0.f;
            }
        }
    };

    stage(0, 0);
    CP_COMMIT();

    for (int c = 0; c < nChunks; c++) {
        const int buf = c & 1;
        if (c + 1 < nChunks) {
            stage(c + 1, buf ^ 1);
            CP_COMMIT();
            CP_WAIT(1);
        } else {
            CP_WAIT(0);
        }
        __syncthreads();
#pragma unroll
        for (int kt = 0; kt < 4; kt++) {
            wmma::fragment<wmma::matrix_a, 16, 16, 8, wmma::precision::tf32, wmma::row_major> af0, af1;
            wmma::fragment<wmma::matrix_b, 16, 16, 8, wmma::precision::tf32, wmma::col_major> bf;
            wmma::load_matrix_sync(af0, &As[buf][(wm * 32) * 36 + kt * 8], 36);
            wmma::load_matrix_sync(af1, &As[buf][(wm * 32 + 16) * 36 + kt * 8], 36);
            wmma::load_matrix_sync(bf,  &Bs[buf][(wn * 16) * 36 + kt * 8], 36);
            wmma::mma_sync(acc0, af0, bf, acc0);
            wmma::mma_sync(acc1, af1, bf, acc1);
        }
        __syncthreads();
    }

#pragma unroll
    for (int i = 0; i < acc0.num_elements; i++) {
        float v0 = acc0.x[i], v1 = acc1.x[i];
        if (doLeaky) { v0 = leaky(v0); v1 = leaky(v1); }
        if (outCvt)  { v0 = tf32f(v0); v1 = tf32f(v1); }
        acc0.x[i] = v0; acc1.x[i] = v1;
    }
    wmma::store_matrix_sync(C + (long long)(m0 + wm * 32) * N + n0 + wn * 16,
                            acc0, N, wmma::mem_row_major);
    wmma::store_matrix_sync(C + (long long)(m0 + wm * 32 + 16) * N + n0 + wn * 16,
                            acc1, N, wmma::mem_row_major);
}

// ---------------- launch ----------------
extern "C" void kernel_launch(void* const* d_in, const int* in_sizes, int n_in,
                              void* d_out, int out_size)
{
    const float* x          = (const float*)d_in[0];
    const int*   edge_index = (const int*)d_in[1];
    const float* edge_attr  = (const float*)d_in[2];
    const float* Wm1 = (const float*)d_in[3];
    const float* bm1 = (const float*)d_in[4];
    const float* Wm2 = (const float*)d_in[5];
    const float* bm2 = (const float*)d_in[6];
    const float* Wm3 = (const float*)d_in[7];
    const float* bm3 = (const float*)d_in[8];
    const float* ln_g = (const float*)d_in[9];
    const float* ln_b = (const float*)d_in[10];
    const float* Wu1 = (const float*)d_in[11];
    const float* bu1 = (const float*)d_in[12];
    const float* Wu2 = (const float*)d_in[13];
    const float* bu2 = (const float*)d_in[14];
    const float* Wu3 = (const float*)d_in[15];
    const float* bu3 = (const float*)d_in[16];
    float* out = (float*)d_out;

    void *p_nrm = nullptr, *p_u1 = nullptr, *p_u2 = nullptr;
    void *p_w1 = nullptr, *p_w2 = nullptr, *p_w3 = nullptr;
    cudaGetSymbolAddress(&p_nrm, g_nrm);
    cudaGetSymbolAddress(&p_u1,  g_u1);
    cudaGetSymbolAddress(&p_u2,  g_u2);
    cudaGetSymbolAddress(&p_w1,  g_w1t);
    cudaGetSymbolAddress(&p_w2,  g_w2t);
    cudaGetSymbolAddress(&p_w3,  g_w3t);

    cudaFuncSetAttribute(k_edge, cudaFuncAttributeMaxDynamicSharedMemorySize, EDGE_SMEM_BYTES);

    k_zero<<<2048, 256>>>();
    k_prep<<<64, 256>>>(Wu1, Wu2, Wu3);
    k_nop<<<1, 32>>>();

    k_edge<<<EGRID, 256, EDGE_SMEM_BYTES>>>(edge_attr, edge_index,
                                            Wm1, bm1, Wm2, bm2, Wm3, bm3);

    k_ln<<<(N_NODES * 32 + 255) / 256, 256>>>(x, ln_g, ln_b);

    dim3 g1((N_NODES + 63) / 64, (D_U1 + 63) / 64);
    k_wgemm<<<g1, 256>>>((const float*)p_nrm, (const float*)p_w1, bu1, (float*)p_u1,
                         N_NODES, D_U1, D_CAT, 1, 1);

    dim3 g2((N_NODES + 63) / 64, (D_U2 + 63) / 64);
    k_wgemm<<<g2, 256>>>((const float*)p_u1, (const float*)p_w2, bu2, (float*)p_u2,
                         N_NODES, D_U2, D_U1, 1, 1);

    dim3 g3((N_NODES + 63) / 64, (D_OUT + 63) / 64);
    k_wgemm<<<g3, 256>>>((const float*)p_u2, (const float*)p_w3, bu3, out,
                         N_NODES, D_OUT, D_U2, 0, 0);
}